// round 1
// baseline (speedup 1.0000x reference)
#include <cuda_runtime.h>
#include <cstdint>

#define BATCH 16
#define MAXGT 64
#define NCLS 80
#define HWTOT 21824

// Output layout (floats), concatenated in reference return order.
#define OFF_CLS_T 0ULL
#define OFF_CLS_M ((size_t)BATCH * HWTOT * NCLS)            // 27,934,720
#define OFF_NP    (OFF_CLS_M + (size_t)BATCH * HWTOT)       // 28,283,904
#define OFF_REG_T (OFF_NP + BATCH)                          // 28,283,920
#define OFF_REG_M (OFF_REG_T + (size_t)BATCH * HWTOT * 4)   // 29,680,656

__global__ void init_np_kernel(float* __restrict__ np) {
    if (threadIdx.x < BATCH) np[threadIdx.x] = 0.0f;
}

// Compute shrunken/clipped region bounds exactly like reference _prop_box.
// Uses __f*_rn intrinsics to forbid FMA contraction (floor/ceil boundary safety).
static __device__ __forceinline__ void prop_bounds(
    float px1, float py1, float px2, float py2, float w, float h,
    float a, float ff,
    int& ox1, int& oy1, int& ox2, int& oy2)
{
    float n1 = floorf(__fadd_rn(px1, __fmul_rn(a, w)));
    float m1 = floorf(__fadd_rn(py1, __fmul_rn(a, h)));
    float n2 = ceilf (__fsub_rn(px2, __fmul_rn(a, w)));
    float m2 = ceilf (__fsub_rn(py2, __fmul_rn(a, h)));
    n2 = fminf(fmaxf(fmaxf(n2, n1 + 1.0f), 0.0f), ff);
    m2 = fminf(fmaxf(fmaxf(m2, m1 + 1.0f), 0.0f), ff);
    n1 = fminf(fmaxf(n1, 0.0f), ff - 1.0f);
    m1 = fminf(fmaxf(m1, 0.0f), ff - 1.0f);
    ox1 = (int)n1; oy1 = (int)m1; ox2 = (int)n2; oy2 = (int)m2;
}

__global__ void __launch_bounds__(256)
fsaf_kernel(const int* __restrict__ g_levels,
            const float* __restrict__ g_boxes,
            float* __restrict__ out)
{
    const int img = blockIdx.y;
    const int bx  = blockIdx.x;

    // Block -> (level, tile). Tiles of 256 cells: {64,16,4,1,1} per level.
    int lvl, tile;
    if      (bx < 64) { lvl = 0; tile = bx;      }
    else if (bx < 80) { lvl = 1; tile = bx - 64; }
    else if (bx < 84) { lvl = 2; tile = bx - 80; }
    else if (bx == 84){ lvl = 3; tile = 0;       }
    else              { lvl = 4; tile = 0;       }

    const int stride = 8 << lvl;       // 8,16,32,64,128
    const int f      = 128 >> lvl;     // 128,64,32,16,8
    const int lg     = 7 - lvl;        // log2(f)
    const int hw     = f * f;
    // cell offset of this level within the 21824-cell concat
    const int cellOffTab[5] = {0, 16384, 20480, 21504, 21760};
    const int cellOff = cellOffTab[lvl];

    // Compacted per-GT data (only GTs whose level == lvl)
    __shared__ int   s_px1[MAXGT], s_py1[MAXGT], s_px2[MAXGT], s_py2[MAXGT]; // pos region
    __shared__ int   s_ix1[MAXGT], s_iy1[MAXGT], s_ix2[MAXGT], s_iy2[MAXGT]; // ignore region
    __shared__ int   s_ux1[MAXGT], s_uy1[MAXGT], s_ux2[MAXGT], s_uy2[MAXGT]; // union bbox (skip test)
    __shared__ float s_area[MAXGT];
    __shared__ float s_bx1[MAXGT], s_by1[MAXGT], s_bx2[MAXGT], s_by2[MAXGT]; // image-coord box
    __shared__ int   s_lab[MAXGT];
    __shared__ int   s_n;

    const int tid  = threadIdx.x;
    const int lane = tid & 31;
    const int wid  = tid >> 5;

    // ---- Warp 0: compute + compact GT data (order-preserving) ----
    if (wid == 0) {
        int base = 0;
        #pragma unroll
        for (int half = 0; half < 2; ++half) {
            const int g = half * 32 + lane;
            const float* bp = g_boxes + ((size_t)img * MAXGT + g) * 5;
            float bx1 = bp[0], by1 = bp[1], bx2 = bp[2], by2 = bp[3];
            int   lab = (int)bp[4];
            int   glvl = g_levels[img * MAXGT + g];
            bool  valid = (glvl == lvl);

            const float inv = 1.0f / (float)stride; // exact (power of 2)
            float px1 = bx1 * inv, py1 = by1 * inv, px2 = bx2 * inv, py2 = by2 * inv;
            float w = px2 - px1, h = py2 - py1;
            const float ff = (float)f;

            int pp1x, pp1y, pp2x, pp2y;   // POS_SCALE=0.2 -> a=0.4
            int ii1x, ii1y, ii2x, ii2y;   // IGNORE_SCALE=0.5 -> a=0.25
            prop_bounds(px1, py1, px2, py2, w, h, 0.4f,  ff, pp1x, pp1y, pp2x, pp2y);
            prop_bounds(px1, py1, px2, py2, w, h, 0.25f, ff, ii1x, ii1y, ii2x, ii2y);

            unsigned bm = __ballot_sync(0xffffffffu, valid);
            int pos = base + __popc(bm & ((1u << lane) - 1u));
            if (valid) {
                s_px1[pos] = pp1x; s_py1[pos] = pp1y; s_px2[pos] = pp2x; s_py2[pos] = pp2y;
                s_ix1[pos] = ii1x; s_iy1[pos] = ii1y; s_ix2[pos] = ii2x; s_iy2[pos] = ii2y;
                s_ux1[pos] = min(pp1x, ii1x); s_uy1[pos] = min(pp1y, ii1y);
                s_ux2[pos] = max(pp2x, ii2x); s_uy2[pos] = max(pp2y, ii2y);
                s_area[pos] = (bx2 - bx1) * (by2 - by1);
                s_bx1[pos] = bx1; s_by1[pos] = by1; s_bx2[pos] = bx2; s_by2[pos] = by2;
                s_lab[pos] = lab;
            }
            base += __popc(bm);
        }
        if (lane == 0) s_n = base;
    }
    __syncthreads();
    const int n = s_n;

    // ---- Per-cell assignment ----
    const int cell   = tile * 256 + tid;
    const bool active = (cell < hw);
    const int y = cell >> lg;
    const int x = cell & (f - 1);

    // Warp-uniform bounding range of this warp's 32 consecutive cells
    const int cw0  = (tile * 256 + (wid << 5));
    const int ymin = cw0 >> lg;
    const int ymax = (cw0 + 31) >> lg;
    int xlo, xhi;
    if (ymin == ymax) { xlo = cw0 & (f - 1); xhi = xlo + 31; }
    else              { xlo = 0;             xhi = f - 1;    }

    bool  anyp = false, anyi = false;
    float best = 1.0e10f;
    int   bidx = 0;

    for (int g = 0; g < n; ++g) {
        // Warp-uniform skip: does this GT's (pos U ign) bbox intersect warp range?
        if (s_ux1[g] <= xhi && s_ux2[g] > xlo && s_uy1[g] <= ymax && s_uy2[g] > ymin) {
            bool inp = (x >= s_px1[g]) & (x < s_px2[g]) & (y >= s_py1[g]) & (y < s_py2[g]);
            bool ini = (x >= s_ix1[g]) & (x < s_ix2[g]) & (y >= s_iy1[g]) & (y < s_iy2[g]);
            anyi |= ini;
            float a = s_area[g];
            bool take = inp & (a < best);
            anyp |= inp;
            if (take) { best = a; bidx = g; }
        }
    }

    // num_pos: warp-aggregated exact count
    unsigned pm = __ballot_sync(0xffffffffu, active && anyp);
    if (lane == 0 && pm)
        atomicAdd(out + OFF_NP + img, (float)__popc(pm));

    const size_t imgCell = (size_t)img * HWTOT + cellOff + cell;

    if (active) {
        out[OFF_CLS_M + imgCell] = (anyp || !anyi) ? 1.0f : 0.0f;
        out[OFF_REG_M + imgCell] = anyp ? 1.0f : 0.0f;

        float4 rv = make_float4(0.0f, 0.0f, 0.0f, 0.0f);
        if (anyp) {
            float sx = ((float)x + 0.5f) * (float)stride; // exact
            float sy = ((float)y + 0.5f) * (float)stride;
            rv.x = (sx - s_bx1[bidx]) * 0.25f;
            rv.y = (sy - s_by1[bidx]) * 0.25f;
            rv.z = (s_bx2[bidx] - sx) * 0.25f;
            rv.w = (s_by2[bidx] - sy) * 0.25f;
        }
        reinterpret_cast<float4*>(out + OFF_REG_T)[imgCell] = rv;
    }

    // cls_t: warp-cooperative coalesced zero fill of 32 cells x 80 floats,
    // then scatter the single one-hot element.
    const int cellW0 = tile * 256 + (wid << 5);
    if (cellW0 < hw) { // hw is a multiple of 32 -> whole warp valid together
        float4* basep = reinterpret_cast<float4*>(
            out + OFF_CLS_T + ((size_t)img * HWTOT + cellOff + cellW0) * NCLS);
        const float4 z = make_float4(0.0f, 0.0f, 0.0f, 0.0f);
        #pragma unroll
        for (int i = 0; i < 20; ++i)
            basep[i * 32 + lane] = z;
        __syncwarp();
        if (anyp)
            out[OFF_CLS_T + imgCell * NCLS + s_lab[bidx]] = 1.0f;
    }
}

extern "C" void kernel_launch(void* const* d_in, const int* in_sizes, int n_in,
                              void* d_out, int out_size)
{
    const int*   levels = (const int*)  d_in[0];  // (16,64) int32
    const float* boxes  = (const float*)d_in[1];  // (16,64,5) float32
    // d_in[2] feature_shapes: constant, unused
    float* out = (float*)d_out;

    init_np_kernel<<<1, 32>>>(out + OFF_NP);
    dim3 grid(86, BATCH);
    fsaf_kernel<<<grid, 256>>>(levels, boxes, out);
}